// round 3
// baseline (speedup 1.0000x reference)
#include <cuda_runtime.h>

#define NR   8192
#define NQ   4096
#define KNN_K 16
#define C4   64          // 256 channels / 4 (float4)

// scratch: per-query sorted neighbor indices (ascending distance, tie = lower idx)
__device__ int g_knn_idx[NQ * KNN_K];

__device__ __forceinline__ bool dist_less(float d1, int i1, float d2, int i2) {
    return (d1 < d2) || (d1 == d2 && i1 < i2);
}

// q2/r2: jnp.sum(x*x) = sequential add reduction of rn squares (no FMA).
__device__ __forceinline__ float sq3(float x, float y, float z) {
    return __fadd_rn(__fadd_rn(__fmul_rn(x, x), __fmul_rn(y, y)), __fmul_rn(z, z));
}
// cross: XLA dot accumulation = fmuladd chain over c=0..2.
// fma(q0,r0,0) == rn(q0*r0), so seed with the rounded product.
__device__ __forceinline__ float dot3_fma(float ax, float ay, float az,
                                          float bx, float by, float bz) {
    return __fmaf_rn(az, bz, __fmaf_rn(ay, by, __fmul_rn(ax, bx)));
}

// One warp per query. Refs cached in SMEM (96KB dynamic). Per-lane register
// top-16 via bubble-insert, then 32-way sorted-list merge with warp shuffles.
__global__ void __launch_bounds__(256, 2) knn_kernel(
        const float* __restrict__ xyz_prev,
        const float* __restrict__ xyz_cur) {
    extern __shared__ float sm[];
    float* sx = sm;
    float* sy = sm + NR;
    float* sz = sm + 2 * NR;

    const int tid = threadIdx.x;
    // coalesced load of (NR,3) -> SoA in shared
    for (int i = tid; i < 3 * NR; i += 256) {
        float v = xyz_prev[i];
        int r = i / 3, c = i - 3 * r;
        if (c == 0) sx[r] = v;
        else if (c == 1) sy[r] = v;
        else sz[r] = v;
    }
    __syncthreads();

    const int warp = tid >> 5;
    const int lane = tid & 31;
    const int q = blockIdx.x * 8 + warp;

    const float qx = xyz_cur[3 * q + 0];
    const float qy = xyz_cur[3 * q + 1];
    const float qz = xyz_cur[3 * q + 2];
    const float q2 = sq3(qx, qy, qz);

    float bd[KNN_K];
    int   bi[KNN_K];
#pragma unroll
    for (int i = 0; i < KNN_K; ++i) {
        bd[i] = __int_as_float(0x7f800000);   // +inf
        bi[i] = 0x7fffffff;
    }

    for (int r = lane; r < NR; r += 32) {
        float rx = sx[r], ry = sy[r], rz = sz[r];
        float r2 = sq3(rx, ry, rz);
        float cr = dot3_fma(qx, qy, qz, rx, ry, rz);
        // 2*cross is exact; single rounded subtract matches both XLA forms
        float d = __fsub_rn(__fadd_rn(q2, r2), __fmul_rn(2.0f, cr));
        if (dist_less(d, r, bd[KNN_K - 1], bi[KNN_K - 1])) {
            bd[KNN_K - 1] = d;
            bi[KNN_K - 1] = r;
#pragma unroll
            for (int j = KNN_K - 1; j > 0; --j) {
                if (dist_less(bd[j], bi[j], bd[j - 1], bi[j - 1])) {
                    float td = bd[j]; bd[j] = bd[j - 1]; bd[j - 1] = td;
                    int   ti = bi[j]; bi[j] = bi[j - 1]; bi[j - 1] = ti;
                }
            }
        }
    }

    __syncthreads();   // everyone is done reading refs; reuse SMEM for merge slots

    float* md = sm;                // 256 threads * 16 = 4096 floats
    int*   mi = (int*)(sm + NR);   // disjoint region
    const int base = tid * KNN_K;
#pragma unroll
    for (int i = 0; i < KNN_K; ++i) { md[base + i] = bd[i]; mi[base + i] = bi[i]; }

    // 32-way merge of per-lane sorted lists; 16 selection rounds
    int p = 0;
    for (int r = 0; r < KNN_K; ++r) {
        float d  = (p < KNN_K) ? md[base + p] : __int_as_float(0x7f800000);
        int   ix = (p < KNN_K) ? mi[base + p] : 0x7fffffff;
        int   ln = lane;
#pragma unroll
        for (int off = 16; off > 0; off >>= 1) {
            float od = __shfl_down_sync(0xffffffffu, d, off);
            int   oi = __shfl_down_sync(0xffffffffu, ix, off);
            int   ol = __shfl_down_sync(0xffffffffu, ln, off);
            if (dist_less(od, oi, d, ix)) { d = od; ix = oi; ln = ol; }
        }
        int wi = __shfl_sync(0xffffffffu, ix, 0);
        int wl = __shfl_sync(0xffffffffu, ln, 0);
        if (lane == wl) ++p;
        if (lane == 0) g_knn_idx[q * KNN_K + r] = wi;
    }
}

// One block per query. blockDim = (64, 4). Each thread owns one float4 channel
// group; cur features held in registers and reused across 4 neighbors.
// Output row (q*16 + j): [prev[idx]-cur (256 f32) | cur (256 f32)]
__global__ void __launch_bounds__(256) gather_kernel(
        const float4* __restrict__ feat_prev,
        const float4* __restrict__ feat_cur,
        float4* __restrict__ out) {
    const int q  = blockIdx.x;
    const int c4 = threadIdx.x;   // 0..63
    const int y  = threadIdx.y;   // 0..3

    const float4 cur = feat_cur[q * C4 + c4];

#pragma unroll
    for (int jj = 0; jj < 4; ++jj) {
        const int j = jj * 4 + y;
        const int idx = __ldg(&g_knn_idx[q * KNN_K + j]);
        const float4 p = feat_prev[idx * C4 + c4];
        float4 dv;
        dv.x = p.x - cur.x; dv.y = p.y - cur.y;
        dv.z = p.z - cur.z; dv.w = p.w - cur.w;
        const int row = q * KNN_K + j;          // 0..65535
        out[row * 128 + c4]      = dv;          // diff half
        out[row * 128 + C4 + c4] = cur;         // copy half
    }
}

extern "C" void kernel_launch(void* const* d_in, const int* in_sizes, int n_in,
                              void* d_out, int out_size) {
    const float*  xyz_prev  = (const float*)d_in[0];
    const float*  xyz_cur   = (const float*)d_in[1];
    const float4* feat_prev = (const float4*)d_in[2];
    const float4* feat_cur  = (const float4*)d_in[3];
    float4* out = (float4*)d_out;

    (void)in_sizes; (void)n_in; (void)out_size;

    const int smem = 3 * NR * sizeof(float);   // 96 KB
    cudaFuncSetAttribute(knn_kernel, cudaFuncAttributeMaxDynamicSharedMemorySize, smem);

    knn_kernel<<<NQ / 8, 256, smem>>>(xyz_prev, xyz_cur);
    gather_kernel<<<NQ, dim3(64, 4)>>>(feat_prev, feat_cur, out);
}

// round 4
// speedup vs baseline: 4.6020x; 4.6020x over previous
#include <cuda_runtime.h>

#define NR    8192
#define NQ    4096
#define KNN_K 16
#define C4    64           // 256 channels / 4 (float4)

#define WARPS_PER_BLOCK 16
#define KNN_THREADS     (WARPS_PER_BLOCK * 32)
#define KNN_BLOCKS      (NQ / WARPS_PER_BLOCK)
#define SAMPLE_ITERS    128        // phase-1 samples 32*128 = 4096 refs
#define FULL_ITERS      (NR / 32)  // 256
#define BUF_CAP         512

typedef unsigned long long ull;

__device__ int    g_knn_idx[NQ * KNN_K];
__device__ float4 g_ref4[NR];          // (x, y, z, r2)

// q2/r2: jnp.sum(x*x) = sequential add of rn squares (no FMA).
__device__ __forceinline__ float sq3(float x, float y, float z) {
    return __fadd_rn(__fadd_rn(__fmul_rn(x, x), __fmul_rn(y, y)), __fmul_rn(z, z));
}
// cross: XLA dot accumulation = fmuladd chain (seed = rn product).
__device__ __forceinline__ float dot3_fma(float ax, float ay, float az,
                                          float bx, float by, float bz) {
    return __fmaf_rn(az, bz, __fmaf_rn(ay, by, __fmul_rn(ax, bx)));
}

// Lexicographic (dist, idx) as one sortable u64. Handles negative dists.
__device__ __forceinline__ ull make_key(float d, int r) {
    unsigned b = __float_as_uint(d);
    b ^= ((unsigned)((int)b >> 31)) | 0x80000000u;
    return ((ull)b << 32) | (unsigned)r;
}

__global__ void pack_kernel(const float* __restrict__ xyz_prev) {
    int r = blockIdx.x * 256 + threadIdx.x;
    if (r < NR) {
        float x = xyz_prev[3 * r + 0];
        float y = xyz_prev[3 * r + 1];
        float z = xyz_prev[3 * r + 2];
        g_ref4[r] = make_float4(x, y, z, sq3(x, y, z));
    }
}

// One warp per query. Two-pass: sampled lane-min -> bitonic -> threshold tau;
// full scan ballot-compacts survivors; 16 argmin rounds extract the answer.
__global__ void __launch_bounds__(KNN_THREADS, 1) knn_kernel(
        const float* __restrict__ xyz_cur) {
    extern __shared__ unsigned char smraw[];
    float4* sref = (float4*)smraw;                         // 128 KB
    ull*    bufs = (ull*)(smraw + NR * sizeof(float4));    // 16 warps * 512 * 8B

    const int tid = threadIdx.x;
    for (int i = tid; i < NR; i += KNN_THREADS) sref[i] = g_ref4[i];
    __syncthreads();

    const int warp = tid >> 5;
    const int lane = tid & 31;
    const int q = blockIdx.x * WARPS_PER_BLOCK + warp;
    ull* wbuf = bufs + warp * BUF_CAP;

    const float qx = xyz_cur[3 * q + 0];
    const float qy = xyz_cur[3 * q + 1];
    const float qz = xyz_cur[3 * q + 2];
    const float q2 = sq3(qx, qy, qz);

    // ---- Phase 1: per-lane min over 128 sampled refs ----
    ull mink = ~0ull;
#pragma unroll 4
    for (int i = 0; i < SAMPLE_ITERS; ++i) {
        const int r = lane + 32 * i;
        const float4 p = sref[r];
        const float cr = dot3_fma(qx, qy, qz, p.x, p.y, p.z);
        const float s  = __fadd_rn(q2, p.w);
        const float d  = __fmaf_rn(-2.0f, cr, s);   // == rn(s - 2*cr)
        const ull k = make_key(d, r);
        if (k < mink) mink = k;
    }

    // bitonic sort the 32 lane minima (ascending by lane); tau = 16th smallest
    ull kv = mink;
#pragma unroll
    for (int kk = 2; kk <= 32; kk <<= 1) {
#pragma unroll
        for (int j = kk >> 1; j > 0; j >>= 1) {
            ull o = __shfl_xor_sync(0xffffffffu, kv, j);
            bool up = ((lane & kk) == 0);
            bool low = ((lane & j) == 0);
            bool takeMin = (low == up);
            ull mn = (kv < o) ? kv : o;
            ull mx = (kv < o) ? o : kv;
            kv = takeMin ? mn : mx;
        }
    }
    const ull tau = __shfl_sync(0xffffffffu, kv, KNN_K - 1);

    // ---- Phase 2: full scan, compact survivors (key <= tau) ----
    int base = 0;
    const unsigned lt_mask = (1u << lane) - 1u;
#pragma unroll 4
    for (int i = 0; i < FULL_ITERS; ++i) {
        const int r = lane + 32 * i;
        const float4 p = sref[r];
        const float cr = dot3_fma(qx, qy, qz, p.x, p.y, p.z);
        const float s  = __fadd_rn(q2, p.w);
        const float d  = __fmaf_rn(-2.0f, cr, s);
        const ull k = make_key(d, r);
        const bool pred = (k <= tau);
        const unsigned m = __ballot_sync(0xffffffffu, pred);
        if (m) {
            if (pred) {
                int pos = base + __popc(m & lt_mask);
                if (pos < BUF_CAP) wbuf[pos] = k;
            }
            base += __popc(m);
        }
    }
    const int cnt = (base < BUF_CAP) ? base : BUF_CAP;   // >= 16 guaranteed
    __syncwarp();

    // ---- Phase 3: 16 argmin-extract rounds over the small buffer ----
    for (int sel = 0; sel < KNN_K; ++sel) {
        ull best = ~0ull;
        int bpos = -1;
        for (int i = lane; i < cnt; i += 32) {
            ull v = wbuf[i];
            if (v < best) { best = v; bpos = i; }
        }
#pragma unroll
        for (int off = 16; off > 0; off >>= 1) {
            ull ob = __shfl_down_sync(0xffffffffu, best, off);
            int op = __shfl_down_sync(0xffffffffu, bpos, off);
            if (ob < best) { best = ob; bpos = op; }
        }
        bpos = __shfl_sync(0xffffffffu, bpos, 0);
        if (lane == 0) {
            best = __shfl_sync(0xffffffffu, best, 0);
            g_knn_idx[q * KNN_K + sel] = (int)(best & 0xffffffffu);
            wbuf[bpos] = ~0ull;
        } else {
            __shfl_sync(0xffffffffu, best, 0);
        }
        __syncwarp();
    }
}

// One block per query. blockDim = (64, 4). cur features in registers, reused
// across 4 neighbors. Output row (q*16+j): [prev[idx]-cur | cur], 512 f32.
__global__ void __launch_bounds__(256) gather_kernel(
        const float4* __restrict__ feat_prev,
        const float4* __restrict__ feat_cur,
        float4* __restrict__ out) {
    const int q  = blockIdx.x;
    const int c4 = threadIdx.x;   // 0..63
    const int y  = threadIdx.y;   // 0..3

    const float4 cur = feat_cur[q * C4 + c4];

#pragma unroll
    for (int jj = 0; jj < 4; ++jj) {
        const int j = jj * 4 + y;
        const int idx = __ldg(&g_knn_idx[q * KNN_K + j]);
        const float4 p = feat_prev[idx * C4 + c4];
        float4 dv;
        dv.x = p.x - cur.x; dv.y = p.y - cur.y;
        dv.z = p.z - cur.z; dv.w = p.w - cur.w;
        const int row = q * KNN_K + j;          // 0..65535
        __stcs(&out[row * 128 + c4], dv);
        __stcs(&out[row * 128 + C4 + c4], cur);
    }
}

extern "C" void kernel_launch(void* const* d_in, const int* in_sizes, int n_in,
                              void* d_out, int out_size) {
    const float*  xyz_prev  = (const float*)d_in[0];
    const float*  xyz_cur   = (const float*)d_in[1];
    const float4* feat_prev = (const float4*)d_in[2];
    const float4* feat_cur  = (const float4*)d_in[3];
    float4* out = (float4*)d_out;

    (void)in_sizes; (void)n_in; (void)out_size;

    const int smem = NR * sizeof(float4) + WARPS_PER_BLOCK * BUF_CAP * sizeof(ull);
    cudaFuncSetAttribute(knn_kernel, cudaFuncAttributeMaxDynamicSharedMemorySize, smem);

    pack_kernel<<<(NR + 255) / 256, 256>>>(xyz_prev);
    knn_kernel<<<KNN_BLOCKS, KNN_THREADS, smem>>>(xyz_cur);
    gather_kernel<<<NQ, dim3(64, 4)>>>(feat_prev, feat_cur, out);
}

// round 5
// speedup vs baseline: 7.6691x; 1.6665x over previous
#include <cuda_runtime.h>

#define NR    8192
#define NQ    4096
#define KNN_K 16
#define C4    64           // 256 channels / 4 (float4)

#define WARPS_PER_BLOCK 28
#define KNN_THREADS     (WARPS_PER_BLOCK * 32)          // 896
#define KNN_BLOCKS      ((NQ + WARPS_PER_BLOCK - 1) / WARPS_PER_BLOCK)  // 147
#define SAMPLE_ITERS    64         // phase-1 samples 32*64 = 2048 refs
#define FULL_ITERS      (NR / 32)  // 256
#define BUF_CAP         256

typedef unsigned long long ull;

__device__ int g_knn_idx[NQ * KNN_K];

// q2/r2: jnp.sum(x*x) = sequential add of rn squares (no FMA).
__device__ __forceinline__ float sq3(float x, float y, float z) {
    return __fadd_rn(__fadd_rn(__fmul_rn(x, x), __fmul_rn(y, y)), __fmul_rn(z, z));
}
// cross: XLA dot accumulation = fmuladd chain (seed = rn product).
__device__ __forceinline__ float dot3_fma(float ax, float ay, float az,
                                          float bx, float by, float bz) {
    return __fmaf_rn(az, bz, __fmaf_rn(ay, by, __fmul_rn(ax, bx)));
}
// Lexicographic (dist, idx) as one sortable u64 (buffer / final sort only).
__device__ __forceinline__ ull make_key(float d, int r) {
    unsigned b = __float_as_uint(d);
    b ^= ((unsigned)((int)b >> 31)) | 0x80000000u;
    return ((ull)b << 32) | (unsigned)r;
}
__device__ __forceinline__ bool pair_less(float d1, int i1, float d2, int i2) {
    return (d1 < d2) || (d1 == d2 && i1 < i2);
}

// One warp per query. Refs (x,y,z,r2) staged in SMEM (r2 computed in-fill).
// Two-pass: sampled lane-min -> bitonic -> tau; full scan ballot-compacts
// d <= tau_d survivors (superset of key<=tau); 16 argmin rounds finish.
__global__ void __launch_bounds__(KNN_THREADS, 1) knn_kernel(
        const float* __restrict__ xyz_prev,
        const float* __restrict__ xyz_cur) {
    extern __shared__ unsigned char smraw[];
    float4* sref = (float4*)smraw;                          // 128 KB
    ull*    bufs = (ull*)(smraw + NR * sizeof(float4));     // 28*256*8 = 56 KB

    const int tid = threadIdx.x;
    // fused pack: read xyz triples, compute r2, stage as float4
    for (int i = tid; i < NR; i += KNN_THREADS) {
        float x = xyz_prev[3 * i + 0];
        float y = xyz_prev[3 * i + 1];
        float z = xyz_prev[3 * i + 2];
        sref[i] = make_float4(x, y, z, sq3(x, y, z));
    }
    __syncthreads();

    const int warp = tid >> 5;
    const int lane = tid & 31;
    const int q = blockIdx.x * WARPS_PER_BLOCK + warp;
    if (q >= NQ) return;                    // whole warp exits together
    ull* wbuf = bufs + warp * BUF_CAP;

    const float qx = xyz_cur[3 * q + 0];
    const float qy = xyz_cur[3 * q + 1];
    const float qz = xyz_cur[3 * q + 2];
    const float q2 = sq3(qx, qy, qz);

    // ---- Phase 1: per-lane min over 2048 sampled refs (4 independent accs) ----
    float md0 = __int_as_float(0x7f800000), md1 = md0, md2 = md0, md3 = md0;
    int   mr0 = 0x7fffffff, mr1 = mr0, mr2 = mr0, mr3 = mr0;
#pragma unroll 4
    for (int i = 0; i < SAMPLE_ITERS; i += 4) {
#pragma unroll
        for (int j = 0; j < 4; ++j) {
            const int r = lane + 32 * (i + j);
            const float4 p = sref[r];
            const float cr = dot3_fma(qx, qy, qz, p.x, p.y, p.z);
            const float d  = __fmaf_rn(-2.0f, cr, __fadd_rn(q2, p.w));
            if (j == 0) { if (d < md0) { md0 = d; mr0 = r; } }
            if (j == 1) { if (d < md1) { md1 = d; mr1 = r; } }
            if (j == 2) { if (d < md2) { md2 = d; mr2 = r; } }
            if (j == 3) { if (d < md3) { md3 = d; mr3 = r; } }
        }
    }
    // lexicographic combine (accs may tie across different index ranges)
    float bd = md0; int br = mr0;
    if (pair_less(md1, mr1, bd, br)) { bd = md1; br = mr1; }
    if (pair_less(md2, mr2, bd, br)) { bd = md2; br = mr2; }
    if (pair_less(md3, mr3, bd, br)) { bd = md3; br = mr3; }

    // bitonic sort 32 (d, idx) lane minima ascending; tau = 16th smallest
    float sd = bd; int si = br;
#pragma unroll
    for (int kk = 2; kk <= 32; kk <<= 1) {
#pragma unroll
        for (int j = kk >> 1; j > 0; j >>= 1) {
            float od = __shfl_xor_sync(0xffffffffu, sd, j);
            int   oi = __shfl_xor_sync(0xffffffffu, si, j);
            bool up  = ((lane & kk) == 0);
            bool low = ((lane & j) == 0);
            bool keepMin = (low == up);
            bool oless = pair_less(od, oi, sd, si);
            if (oless == keepMin) { sd = od; si = oi; }
        }
    }
    const float tau_d = __shfl_sync(0xffffffffu, sd, KNN_K - 1);

    // ---- Phase 2: full scan, compact survivors (d <= tau_d) ----
    int base = 0;
    const unsigned lt_mask = (1u << lane) - 1u;
#pragma unroll 4
    for (int i = 0; i < FULL_ITERS; ++i) {
        const int r = lane + 32 * i;
        const float4 p = sref[r];
        const float cr = dot3_fma(qx, qy, qz, p.x, p.y, p.z);
        const float d  = __fmaf_rn(-2.0f, cr, __fadd_rn(q2, p.w));
        const bool pred = (d <= tau_d);
        const unsigned m = __ballot_sync(0xffffffffu, pred);
        if (m) {
            if (pred) {
                int pos = base + __popc(m & lt_mask);
                if (pos < BUF_CAP) wbuf[pos] = make_key(d, r);
            }
            base += __popc(m);
        }
    }
    const int cnt = (base < BUF_CAP) ? base : BUF_CAP;   // >= 16 guaranteed
    __syncwarp();

    // ---- Phase 3: 16 argmin-extract rounds over the small buffer ----
    for (int sel = 0; sel < KNN_K; ++sel) {
        ull best = ~0ull;
        int bpos = -1;
        for (int i = lane; i < cnt; i += 32) {
            ull v = wbuf[i];
            if (v < best) { best = v; bpos = i; }
        }
#pragma unroll
        for (int off = 16; off > 0; off >>= 1) {
            ull ob = __shfl_down_sync(0xffffffffu, best, off);
            int op = __shfl_down_sync(0xffffffffu, bpos, off);
            if (ob < best) { best = ob; bpos = op; }
        }
        bpos = __shfl_sync(0xffffffffu, bpos, 0);
        if (lane == 0) g_knn_idx[q * KNN_K + sel] = (int)(wbuf[bpos] & 0xffffffffu);
        if (lane == (bpos & 31)) wbuf[bpos] = ~0ull;   // any lane may clear; bpos uniform
        __syncwarp();
    }
}

// One block per query. blockDim = (64, 4). cur features in registers, reused
// across 4 neighbors. Output row (q*16+j): [prev[idx]-cur | cur], 512 f32.
__global__ void __launch_bounds__(256) gather_kernel(
        const float4* __restrict__ feat_prev,
        const float4* __restrict__ feat_cur,
        float4* __restrict__ out) {
    const int q  = blockIdx.x;
    const int c4 = threadIdx.x;   // 0..63
    const int y  = threadIdx.y;   // 0..3

    const float4 cur = feat_cur[q * C4 + c4];

#pragma unroll
    for (int jj = 0; jj < 4; ++jj) {
        const int j = jj * 4 + y;
        const int idx = __ldg(&g_knn_idx[q * KNN_K + j]);
        const float4 p = feat_prev[idx * C4 + c4];
        float4 dv;
        dv.x = p.x - cur.x; dv.y = p.y - cur.y;
        dv.z = p.z - cur.z; dv.w = p.w - cur.w;
        const int row = q * KNN_K + j;          // 0..65535
        __stcs(&out[row * 128 + c4], dv);
        __stcs(&out[row * 128 + C4 + c4], cur);
    }
}

extern "C" void kernel_launch(void* const* d_in, const int* in_sizes, int n_in,
                              void* d_out, int out_size) {
    const float*  xyz_prev  = (const float*)d_in[0];
    const float*  xyz_cur   = (const float*)d_in[1];
    const float4* feat_prev = (const float4*)d_in[2];
    const float4* feat_cur  = (const float4*)d_in[3];
    float4* out = (float4*)d_out;

    (void)in_sizes; (void)n_in; (void)out_size;

    const int smem = NR * sizeof(float4) + WARPS_PER_BLOCK * BUF_CAP * sizeof(ull);
    cudaFuncSetAttribute(knn_kernel, cudaFuncAttributeMaxDynamicSharedMemorySize, smem);

    knn_kernel<<<KNN_BLOCKS, KNN_THREADS, smem>>>(xyz_prev, xyz_cur);
    gather_kernel<<<NQ, dim3(64, 4)>>>(feat_prev, feat_cur, out);
}